// round 2
// baseline (speedup 1.0000x reference)
#include <cuda_runtime.h>
#include <cstdint>

#define NN   50000
#define NE   20000
#define NNZV 1600000
#define CH   1024   // concat(4) * hid(256)
#define CIN  256
#define COUT 40

// ---------------- device scratch (static; no allocations) ----------------
__device__ int   g_cnt_v[NN];
__device__ int   g_cnt_e[NE];
__device__ int   g_cur_v[NN];
__device__ int   g_cur_e[NE];
__device__ int   g_off_e[NE];
__device__ int   g_off_n[NN];
__device__ int   g_elist[NNZV];   // nodes grouped by edge
__device__ int   g_nlist[NNZV];   // edges grouped by node
__device__ float g_dvis[NN];
__device__ float g_deinv[NE];
__device__ float g_t1[NE];
__device__ float g_s[NN];
__device__ float g_z [20480000];  // [NE][CH]  de_inv * H^T (dv_is * x)
__device__ float g_z2[20480000];  // [NE][CH]  g_z @ blockdiag(W1)
__device__ float g_hidden[51200000]; // [NN][CH]
__device__ float g_gv[2000000];   // [NN][COUT]
__device__ float g_ef2[800000];   // [NE][COUT]

// ---------------- CSR construction ----------------
__global__ void k_zero() {
    int i = blockIdx.x * blockDim.x + threadIdx.x;
    if (i < NN) { g_cnt_v[i] = 0; g_cur_v[i] = 0; }
    if (i < NE) { g_cnt_e[i] = 0; g_cur_e[i] = 0; }
}

__global__ void k_degree(const int* __restrict__ ni, const int* __restrict__ ei, int nnz) {
    int i = blockIdx.x * blockDim.x + threadIdx.x;
    if (i < nnz) {
        atomicAdd(&g_cnt_v[ni[i]], 1);
        atomicAdd(&g_cnt_e[ei[i]], 1);
    }
}

__global__ void k_dvde() {
    int i = blockIdx.x * blockDim.x + threadIdx.x;
    if (i < NN) {
        int c = g_cnt_v[i];
        g_dvis[i] = (c > 0) ? rsqrtf((float)c) : 0.f;
    }
    if (i < NE) {
        int c = g_cnt_e[i];
        g_deinv[i] = (c > 0) ? 1.f / (float)c : 0.f;
    }
}

__device__ void scan_body(const int* __restrict__ cnt, int* __restrict__ off, int n) {
    __shared__ int buf[1024];
    int t = threadIdx.x;
    int chunk = (n + 1023) >> 10;
    int s0 = t * chunk;
    int sum = 0;
    for (int i = 0; i < chunk; i++) { int idx = s0 + i; if (idx < n) sum += cnt[idx]; }
    buf[t] = sum;
    __syncthreads();
    for (int d = 1; d < 1024; d <<= 1) {
        int add = (t >= d) ? buf[t - d] : 0;
        __syncthreads();
        buf[t] += add;
        __syncthreads();
    }
    int run = buf[t] - sum;
    for (int i = 0; i < chunk; i++) { int idx = s0 + i; if (idx < n) { off[idx] = run; run += cnt[idx]; } }
}
__global__ void k_scan_e() { scan_body(g_cnt_e, g_off_e, NE); }
__global__ void k_scan_n() { scan_body(g_cnt_v, g_off_n, NN); }

__global__ void k_fill(const int* __restrict__ ni, const int* __restrict__ ei, int nnz) {
    int i = blockIdx.x * blockDim.x + threadIdx.x;
    if (i < nnz) {
        int v = ni[i], e = ei[i];
        int p = atomicAdd(&g_cur_e[e], 1);
        g_elist[g_off_e[e] + p] = v;
        int q = atomicAdd(&g_cur_v[v], 1);
        g_nlist[g_off_n[v] + q] = e;
    }
}

// ---------------- s = S * 1  (for bias term) ----------------
__global__ void k_t1() {  // t1[e] = de_inv[e] * sum_{v in e} dv_is[v]
    int e = blockIdx.x, lane = threadIdx.x;
    int beg = g_off_e[e], deg = g_cnt_e[e];
    float acc = 0.f;
    for (int i = lane; i < deg; i += 32) acc += g_dvis[g_elist[beg + i]];
    #pragma unroll
    for (int o = 16; o; o >>= 1) acc += __shfl_down_sync(0xFFFFFFFFu, acc, o);
    if (lane == 0) g_t1[e] = g_deinv[e] * acc;
}
__global__ void k_s() {   // s[v] = dv_is[v] * sum_{e ni v} t1[e]
    int v = blockIdx.x, lane = threadIdx.x;
    int beg = g_off_n[v], deg = g_cnt_v[v];
    float acc = 0.f;
    for (int i = lane; i < deg; i += 32) acc += g_t1[g_nlist[beg + i]];
    #pragma unroll
    for (int o = 16; o; o >>= 1) acc += __shfl_down_sync(0xFFFFFFFFu, acc, o);
    if (lane == 0) g_s[v] = g_dvis[v] * acc;
}

// ---------------- pass A: z[e][:] = de_inv[e] * sum_{v in e} dv_is[v] * x[v][:] ----------------
__global__ void k_passA(const float* __restrict__ x) {
    __shared__ int   svv[256];
    __shared__ float sww[256];
    int e = blockIdx.x, t = threadIdx.x;
    int beg = g_off_e[e], deg = g_cnt_e[e];
    float a0 = 0.f, a1 = 0.f, a2 = 0.f, a3 = 0.f;
    for (int base = 0; base < deg; base += 256) {
        int m = min(256, deg - base);
        __syncthreads();
        if (t < m) {
            int v = g_elist[beg + base + t];
            svv[t] = v;
            sww[t] = g_dvis[v];
        }
        __syncthreads();
        for (int i = 0; i < m; i++) {
            int v = svv[i];
            float w = sww[i];
            const float* xr = x + (size_t)v * CIN + t;
            a0 += w * __ldg(xr);
            a1 += w * __ldg(xr + (size_t)1 * NN * CIN);
            a2 += w * __ldg(xr + (size_t)2 * NN * CIN);
            a3 += w * __ldg(xr + (size_t)3 * NN * CIN);
        }
    }
    float sc = g_deinv[e];
    size_t o = (size_t)e * CH + t;
    g_z[o]       = sc * a0;
    g_z[o + 256] = sc * a1;
    g_z[o + 512] = sc * a2;
    g_z[o + 768] = sc * a3;
}

// ---------------- edge GEMM: z2 = z @ blockdiag(W1[b]) ----------------
__global__ void k_egemm(const float* __restrict__ W1) {
    __shared__ float As[16][64];
    __shared__ float Bs[16][64];
    int b = blockIdx.z;
    int row0 = blockIdx.x * 64;
    int col0 = blockIdx.y * 64;
    int t = threadIdx.x;
    int tx = t & 15, ty = t >> 4;
    float acc[4][4];
    #pragma unroll
    for (int i = 0; i < 4; i++)
        #pragma unroll
        for (int j = 0; j < 4; j++) acc[i][j] = 0.f;
    const float* Wb = W1 + b * 65536;
    for (int k0 = 0; k0 < 256; k0 += 16) {
        #pragma unroll
        for (int i = 0; i < 4; i++) {
            int lin = t + 256 * i;
            int m = lin >> 4, k = lin & 15;
            int r = row0 + m;
            As[k][m] = (r < NE) ? g_z[(size_t)r * CH + b * 256 + k0 + k] : 0.f;
            int n2 = lin & 63, k2 = lin >> 6;
            Bs[k2][n2] = Wb[(k0 + k2) * 256 + col0 + n2];
        }
        __syncthreads();
        #pragma unroll
        for (int k = 0; k < 16; k++) {
            float4 av = *(const float4*)&As[k][ty * 4];
            float4 bv = *(const float4*)&Bs[k][tx * 4];
            acc[0][0] += av.x * bv.x; acc[0][1] += av.x * bv.y; acc[0][2] += av.x * bv.z; acc[0][3] += av.x * bv.w;
            acc[1][0] += av.y * bv.x; acc[1][1] += av.y * bv.y; acc[1][2] += av.y * bv.z; acc[1][3] += av.y * bv.w;
            acc[2][0] += av.z * bv.x; acc[2][1] += av.z * bv.y; acc[2][2] += av.z * bv.z; acc[2][3] += av.z * bv.w;
            acc[3][0] += av.w * bv.x; acc[3][1] += av.w * bv.y; acc[3][2] += av.w * bv.z; acc[3][3] += av.w * bv.w;
        }
        __syncthreads();
    }
    #pragma unroll
    for (int i = 0; i < 4; i++) {
        int r = row0 + ty * 4 + i;
        if (r < NE) {
            size_t o = (size_t)r * CH + b * 256 + col0 + tx * 4;
            #pragma unroll
            for (int j = 0; j < 4; j++) g_z2[o + j] = acc[i][j];
        }
    }
}

// ---------------- pass B: hidden[v][:] = relu(dv_is[v]*sum_{e ni v} z2[e][:] + s[v]*b1[:]) ----------------
__global__ void k_passB(const float* __restrict__ b1) {
    __shared__ int see[256];
    int v = blockIdx.x, t = threadIdx.x;
    int beg = g_off_n[v], deg = g_cnt_v[v];
    float a0 = 0.f, a1 = 0.f, a2 = 0.f, a3 = 0.f;
    for (int base = 0; base < deg; base += 256) {
        int m = min(256, deg - base);
        __syncthreads();
        if (t < m) see[t] = g_nlist[beg + base + t];
        __syncthreads();
        for (int i = 0; i < m; i++) {
            const float* zr = g_z2 + (size_t)see[i] * CH + t;
            a0 += __ldg(zr);
            a1 += __ldg(zr + 256);
            a2 += __ldg(zr + 512);
            a3 += __ldg(zr + 768);
        }
    }
    float w = g_dvis[v], sv = g_s[v];
    size_t o = (size_t)v * CH + t;
    g_hidden[o]       = fmaxf(w * a0 + sv * __ldg(&b1[t]),       0.f);
    g_hidden[o + 256] = fmaxf(w * a1 + sv * __ldg(&b1[t + 256]), 0.f);
    g_hidden[o + 512] = fmaxf(w * a2 + sv * __ldg(&b1[t + 512]), 0.f);
    g_hidden[o + 768] = fmaxf(w * a3 + sv * __ldg(&b1[t + 768]), 0.f);
}

// ---------------- GEMM2: g = hidden[N,1024] @ W2[1024,40] + b2 ----------------
#define GM 96
#define GK 32
__global__ void k_gemm2(const float* __restrict__ W2, const float* __restrict__ b2) {
    __shared__ float Hs[GM][GK + 1];
    __shared__ float Ws[GK][40];
    int row0 = blockIdx.x * GM;
    int t = threadIdx.x;                 // 256 threads; 240 compute
    int tx = t % 10, ty = t / 10;        // tx: 4-col group, ty: 4-row group (ty<24)
    float acc[4][4];
    #pragma unroll
    for (int i = 0; i < 4; i++)
        #pragma unroll
        for (int j = 0; j < 4; j++) acc[i][j] = 0.f;
    for (int k0 = 0; k0 < CH; k0 += GK) {
        #pragma unroll
        for (int i = 0; i < 12; i++) {
            int lin = t + 256 * i;
            int m = lin >> 5, k = lin & 31;
            int r = row0 + m;
            Hs[m][k] = (r < NN) ? g_hidden[(size_t)r * CH + k0 + k] : 0.f;
        }
        #pragma unroll
        for (int i = 0; i < 5; i++) {
            int lin = t + 256 * i;
            int k = lin / 40, j = lin % 40;
            Ws[k][j] = W2[(k0 + k) * 40 + j];
        }
        __syncthreads();
        if (ty < 24) {
            #pragma unroll
            for (int k = 0; k < GK; k++) {
                float4 wv = *(const float4*)&Ws[k][tx * 4];
                #pragma unroll
                for (int i = 0; i < 4; i++) {
                    float a = Hs[ty * 4 + i][k];
                    acc[i][0] += a * wv.x; acc[i][1] += a * wv.y;
                    acc[i][2] += a * wv.z; acc[i][3] += a * wv.w;
                }
            }
        }
        __syncthreads();
    }
    if (ty < 24) {
        #pragma unroll
        for (int i = 0; i < 4; i++) {
            int r = row0 + ty * 4 + i;
            if (r < NN) {
                #pragma unroll
                for (int j = 0; j < 4; j++) {
                    int c = tx * 4 + j;
                    g_gv[(size_t)r * COUT + c] = acc[i][j] + __ldg(&b2[c]);
                }
            }
        }
    }
}

// ---------------- final smooth on [N,40] ----------------
__global__ void k_passCe() {  // ef2[e][j] = de_inv[e] * sum_{v in e} dv_is[v]*g[v][j]
    int e = blockIdx.x, t = threadIdx.x;  // 64 threads, 40 active
    int beg = g_off_e[e], deg = g_cnt_e[e];
    if (t < COUT) {
        float acc = 0.f;
        for (int i = 0; i < deg; i++) {
            int v = g_elist[beg + i];
            acc += __ldg(&g_dvis[v]) * __ldg(&g_gv[(size_t)v * COUT + t]);
        }
        g_ef2[(size_t)e * COUT + t] = g_deinv[e] * acc;
    }
}
__global__ void k_passCn(float* __restrict__ out) {  // out[v][j] = dv_is[v]*sum_{e ni v} ef2[e][j]
    int v = blockIdx.x, t = threadIdx.x;  // 64 threads, 40 active
    int beg = g_off_n[v], deg = g_cnt_v[v];
    if (t < COUT) {
        float acc = 0.f;
        for (int i = 0; i < deg; i++) {
            int e = g_nlist[beg + i];
            acc += __ldg(&g_ef2[(size_t)e * COUT + t]);
        }
        out[(size_t)v * COUT + t] = g_dvis[v] * acc;
    }
}

// ---------------- launch ----------------
extern "C" void kernel_launch(void* const* d_in, const int* in_sizes, int n_in,
                              void* d_out, int out_size) {
    const float* x  = (const float*)d_in[0];   // [4, NN, 256]
    const float* W1 = (const float*)d_in[1];   // [4, 256, 256]
    const float* b1 = (const float*)d_in[2];   // [4, 256] -> flat [1024]
    const float* W2 = (const float*)d_in[3];   // [1024, 40]
    const float* b2 = (const float*)d_in[4];   // [40]
    const int*   ni = (const int*)d_in[5];     // node_idx [NNZ]
    const int*   ei = (const int*)d_in[6];     // edge_idx [NNZ]
    int nnz = in_sizes[5];
    float* out = (float*)d_out;

    k_zero  <<<(NN + 255) / 256, 256>>>();
    k_degree<<<(nnz + 255) / 256, 256>>>(ni, ei, nnz);
    k_dvde  <<<(NN + 255) / 256, 256>>>();
    k_scan_e<<<1, 1024>>>();
    k_scan_n<<<1, 1024>>>();
    k_fill  <<<(nnz + 255) / 256, 256>>>(ni, ei, nnz);
    k_t1    <<<NE, 32>>>();
    k_s     <<<NN, 32>>>();
    k_passA <<<NE, 256>>>(x);
    {
        dim3 grid((NE + 63) / 64, 4, 4);
        k_egemm<<<grid, 256>>>(W1);
    }
    k_passB <<<NN, 256>>>(b1);
    k_gemm2 <<<(NN + GM - 1) / GM, 256>>>(W2, b2);
    k_passCe<<<NE, 64>>>();
    k_passCn<<<NN, 64>>>(out);
}

// round 3
// speedup vs baseline: 1.5599x; 1.5599x over previous
#include <cuda_runtime.h>
#include <cstdint>

#define NN   50000
#define NE   20000
#define NNZV 1600000
#define CH   1024   // concat(4) * hid(256)
#define CIN  256
#define COUT 40

// ---------------- device scratch (static; no allocations) ----------------
__device__ int   g_cnt_v[NN];
__device__ int   g_cnt_e[NE];
__device__ int   g_cur_v[NN];
__device__ int   g_cur_e[NE];
__device__ int   g_off_e[NE];
__device__ int   g_off_n[NN];
__device__ int   g_elist[NNZV];   // nodes grouped by edge
__device__ int   g_nlist[NNZV];   // edges grouped by node
__device__ float g_dvis[NN];
__device__ float g_deinv[NE];
__device__ float g_t1[NE];
__device__ float g_s[NN];
__device__ float g_z [20480000];  // [NE][CH]  de_inv * H^T (dv_is * x)
__device__ float g_z2[20480000];  // [NE][CH]  g_z @ blockdiag(W1)
__device__ float g_hidden[51200000]; // [NN][CH]
__device__ float g_gv[2000000];   // [NN][COUT]
__device__ float g_ef2[800000];   // [NE][COUT]

// ---------------- f32x2 packed math helpers ----------------
__device__ __forceinline__ void ffma2(unsigned long long &d, unsigned long long a, unsigned long long b) {
    asm("fma.rn.f32x2 %0, %1, %2, %0;" : "+l"(d) : "l"(a), "l"(b));
}
__device__ __forceinline__ unsigned long long bcast2(float x) {
    unsigned long long r;
    asm("mov.b64 %0, {%1, %1};" : "=l"(r) : "f"(x));
    return r;
}
__device__ __forceinline__ float lo32(unsigned long long v) { return __uint_as_float((unsigned)v); }
__device__ __forceinline__ float hi32(unsigned long long v) { return __uint_as_float((unsigned)(v >> 32)); }

// ---------------- CSR construction ----------------
__global__ void k_zero() {
    int i = blockIdx.x * blockDim.x + threadIdx.x;
    if (i < NN) { g_cnt_v[i] = 0; g_cur_v[i] = 0; }
    if (i < NE) { g_cnt_e[i] = 0; g_cur_e[i] = 0; }
}

__global__ void k_degree(const int* __restrict__ ni, const int* __restrict__ ei, int nnz) {
    int i = blockIdx.x * blockDim.x + threadIdx.x;
    if (i < nnz) {
        atomicAdd(&g_cnt_v[ni[i]], 1);
        atomicAdd(&g_cnt_e[ei[i]], 1);
    }
}

__global__ void k_dvde() {
    int i = blockIdx.x * blockDim.x + threadIdx.x;
    if (i < NN) {
        int c = g_cnt_v[i];
        g_dvis[i] = (c > 0) ? rsqrtf((float)c) : 0.f;
    }
    if (i < NE) {
        int c = g_cnt_e[i];
        g_deinv[i] = (c > 0) ? 1.f / (float)c : 0.f;
    }
}

__device__ void scan_body(const int* __restrict__ cnt, int* __restrict__ off, int n) {
    __shared__ int warpsum[32];
    int t = threadIdx.x;
    int lane = t & 31, wid = t >> 5;
    int chunk = (n + 1023) >> 10;
    int s0 = t * chunk;
    int sum = 0;
    for (int i = 0; i < chunk; i++) { int idx = s0 + i; if (idx < n) sum += cnt[idx]; }
    // inclusive warp scan of per-thread sums
    int v = sum;
    #pragma unroll
    for (int o = 1; o < 32; o <<= 1) {
        int u = __shfl_up_sync(0xFFFFFFFFu, v, o);
        if (lane >= o) v += u;
    }
    if (lane == 31) warpsum[wid] = v;
    __syncthreads();
    if (wid == 0) {
        int w = warpsum[lane];
        #pragma unroll
        for (int o = 1; o < 32; o <<= 1) {
            int u = __shfl_up_sync(0xFFFFFFFFu, w, o);
            if (lane >= o) w += u;
        }
        warpsum[lane] = w;
    }
    __syncthreads();
    int excl = v - sum + ((wid > 0) ? warpsum[wid - 1] : 0);
    int run = excl;
    for (int i = 0; i < chunk; i++) { int idx = s0 + i; if (idx < n) { off[idx] = run; run += cnt[idx]; } }
}
__global__ void k_scan_e() { scan_body(g_cnt_e, g_off_e, NE); }
__global__ void k_scan_n() { scan_body(g_cnt_v, g_off_n, NN); }

__global__ void k_fill(const int* __restrict__ ni, const int* __restrict__ ei, int nnz) {
    int i = blockIdx.x * blockDim.x + threadIdx.x;
    if (i < nnz) {
        int v = ni[i], e = ei[i];
        int p = atomicAdd(&g_cur_e[e], 1);
        g_elist[g_off_e[e] + p] = v;
        int q = atomicAdd(&g_cur_v[v], 1);
        g_nlist[g_off_n[v] + q] = e;
    }
}

// ---------------- s = S * 1  (for bias term) ----------------
__global__ void k_t1() {
    int e = blockIdx.x, lane = threadIdx.x;
    int beg = g_off_e[e], deg = g_cnt_e[e];
    float acc = 0.f;
    for (int i = lane; i < deg; i += 32) acc += g_dvis[g_elist[beg + i]];
    #pragma unroll
    for (int o = 16; o; o >>= 1) acc += __shfl_down_sync(0xFFFFFFFFu, acc, o);
    if (lane == 0) g_t1[e] = g_deinv[e] * acc;
}
__global__ void k_s() {
    int v = blockIdx.x, lane = threadIdx.x;
    int beg = g_off_n[v], deg = g_cnt_v[v];
    float acc = 0.f;
    for (int i = lane; i < deg; i += 32) acc += g_t1[g_nlist[beg + i]];
    #pragma unroll
    for (int o = 16; o; o >>= 1) acc += __shfl_down_sync(0xFFFFFFFFu, acc, o);
    if (lane == 0) g_s[v] = g_dvis[v] * acc;
}

// ---------------- pass A: z[e][:] = de_inv[e] * sum_{v in e} dv_is[v] * x[v][:] ----------------
// 256 threads: thread t owns global channels [4t, 4t+4). Branch b = t>>6, in-branch col = (t&63)*4.
__global__ void k_passA(const float* __restrict__ x) {
    __shared__ int   svv[128];
    __shared__ float sww[128];
    int e = blockIdx.x, t = threadIdx.x;
    int beg = g_off_e[e], deg = g_cnt_e[e];
    int b = t >> 6, c = (t & 63) * 4;
    const float* xb = x + (size_t)b * NN * CIN + c;
    float4 acc = make_float4(0.f, 0.f, 0.f, 0.f);
    for (int base = 0; base < deg; base += 128) {
        int m = min(128, deg - base);
        __syncthreads();
        if (t < m) {
            int v = g_elist[beg + base + t];
            svv[t] = v;
            sww[t] = g_dvis[v];
        }
        __syncthreads();
        #pragma unroll 4
        for (int i = 0; i < m; i++) {
            float w = sww[i];
            float4 xv = *(const float4*)(xb + (size_t)svv[i] * CIN);
            acc.x += w * xv.x; acc.y += w * xv.y; acc.z += w * xv.z; acc.w += w * xv.w;
        }
    }
    float sc = g_deinv[e];
    float4 o = make_float4(sc * acc.x, sc * acc.y, sc * acc.z, sc * acc.w);
    *(float4*)&g_z[(size_t)e * CH + t * 4] = o;
}

// ---------------- edge GEMM: z2 = z @ blockdiag(W1[b]), packed f32x2 FMAs ----------------
// 128x64 tile, 256 threads, 8 rows x 4 cols per thread (4 u64 row-pairs x 4 cols).
__global__ void k_egemm(const float* __restrict__ W1) {
    __shared__ __align__(16) float As[16][130];  // pad 130: conflict-free STS, 8B-aligned u64 LDS
    __shared__ float Bs[16][64];
    int b = blockIdx.z;
    int row0 = blockIdx.x * 128;
    int col0 = blockIdx.y * 64;
    int t = threadIdx.x;
    int tx = t & 15, ty = t >> 4;
    unsigned long long acc[4][4];
    #pragma unroll
    for (int p = 0; p < 4; p++)
        #pragma unroll
        for (int j = 0; j < 4; j++) acc[p][j] = 0ull;
    const float* Wb = W1 + b * 65536;
    for (int k0 = 0; k0 < 256; k0 += 16) {
        #pragma unroll
        for (int i = 0; i < 8; i++) {
            int lin = t + 256 * i;
            int m = lin >> 4, k = lin & 15;
            int r = row0 + m;
            As[k][m] = (r < NE) ? g_z[(size_t)r * CH + b * 256 + k0 + k] : 0.f;
        }
        #pragma unroll
        for (int i = 0; i < 4; i++) {
            int lin = t + 256 * i;
            int k2 = lin >> 6, n2 = lin & 63;
            Bs[k2][n2] = Wb[(k0 + k2) * 256 + col0 + n2];
        }
        __syncthreads();
        #pragma unroll
        for (int k = 0; k < 16; k++) {
            unsigned long long a0 = *(const unsigned long long*)&As[k][ty * 8 + 0];
            unsigned long long a1 = *(const unsigned long long*)&As[k][ty * 8 + 2];
            unsigned long long a2 = *(const unsigned long long*)&As[k][ty * 8 + 4];
            unsigned long long a3 = *(const unsigned long long*)&As[k][ty * 8 + 6];
            float4 bv = *(const float4*)&Bs[k][tx * 4];
            unsigned long long b0 = bcast2(bv.x), b1 = bcast2(bv.y);
            unsigned long long b2 = bcast2(bv.z), b3 = bcast2(bv.w);
            ffma2(acc[0][0], a0, b0); ffma2(acc[0][1], a0, b1); ffma2(acc[0][2], a0, b2); ffma2(acc[0][3], a0, b3);
            ffma2(acc[1][0], a1, b0); ffma2(acc[1][1], a1, b1); ffma2(acc[1][2], a1, b2); ffma2(acc[1][3], a1, b3);
            ffma2(acc[2][0], a2, b0); ffma2(acc[2][1], a2, b1); ffma2(acc[2][2], a2, b2); ffma2(acc[2][3], a2, b3);
            ffma2(acc[3][0], a3, b0); ffma2(acc[3][1], a3, b1); ffma2(acc[3][2], a3, b2); ffma2(acc[3][3], a3, b3);
        }
        __syncthreads();
    }
    #pragma unroll
    for (int p = 0; p < 4; p++) {
        int r0 = row0 + ty * 8 + 2 * p;
        float4 vlo, vhi;
        vlo.x = lo32(acc[p][0]); vlo.y = lo32(acc[p][1]); vlo.z = lo32(acc[p][2]); vlo.w = lo32(acc[p][3]);
        vhi.x = hi32(acc[p][0]); vhi.y = hi32(acc[p][1]); vhi.z = hi32(acc[p][2]); vhi.w = hi32(acc[p][3]);
        size_t cb = (size_t)b * 256 + col0 + tx * 4;
        if (r0 < NE)     *(float4*)&g_z2[(size_t)r0 * CH + cb]       = vlo;
        if (r0 + 1 < NE) *(float4*)&g_z2[(size_t)(r0 + 1) * CH + cb] = vhi;
    }
}

// ---------------- pass B: hidden[v][:] = relu(dv_is[v]*sum_{e ni v} z2[e][:] + s[v]*b1[:]) ----------------
__global__ void k_passB(const float* __restrict__ b1) {
    __shared__ int see[128];
    int v = blockIdx.x, t = threadIdx.x;
    int beg = g_off_n[v], deg = g_cnt_v[v];
    float4 acc = make_float4(0.f, 0.f, 0.f, 0.f);
    for (int base = 0; base < deg; base += 128) {
        int m = min(128, deg - base);
        __syncthreads();
        if (t < m) see[t] = g_nlist[beg + base + t];
        __syncthreads();
        #pragma unroll 4
        for (int i = 0; i < m; i++) {
            float4 zv = *(const float4*)&g_z2[(size_t)see[i] * CH + t * 4];
            acc.x += zv.x; acc.y += zv.y; acc.z += zv.z; acc.w += zv.w;
        }
    }
    float w = g_dvis[v], sv = g_s[v];
    float4 bb = *(const float4*)&b1[t * 4];
    float4 o;
    o.x = fmaxf(w * acc.x + sv * bb.x, 0.f);
    o.y = fmaxf(w * acc.y + sv * bb.y, 0.f);
    o.z = fmaxf(w * acc.z + sv * bb.z, 0.f);
    o.w = fmaxf(w * acc.w + sv * bb.w, 0.f);
    *(float4*)&g_hidden[(size_t)v * CH + t * 4] = o;
}

// ---------------- GEMM2: g = hidden[N,1024] @ W2[1024,40] + b2 ----------------
#define GM 96
#define GK 32
__global__ void k_gemm2(const float* __restrict__ W2, const float* __restrict__ b2) {
    __shared__ float Hs[GM][GK + 1];
    __shared__ float Ws[GK][40];
    int row0 = blockIdx.x * GM;
    int t = threadIdx.x;
    int tx = t % 10, ty = t / 10;
    float acc[4][4];
    #pragma unroll
    for (int i = 0; i < 4; i++)
        #pragma unroll
        for (int j = 0; j < 4; j++) acc[i][j] = 0.f;
    for (int k0 = 0; k0 < CH; k0 += GK) {
        #pragma unroll
        for (int i = 0; i < 12; i++) {
            int lin = t + 256 * i;
            int m = lin >> 5, k = lin & 31;
            int r = row0 + m;
            Hs[m][k] = (r < NN) ? g_hidden[(size_t)r * CH + k0 + k] : 0.f;
        }
        #pragma unroll
        for (int i = 0; i < 5; i++) {
            int lin = t + 256 * i;
            int k = lin / 40, j = lin % 40;
            Ws[k][j] = W2[(k0 + k) * 40 + j];
        }
        __syncthreads();
        if (ty < 24) {
            #pragma unroll
            for (int k = 0; k < GK; k++) {
                float4 wv = *(const float4*)&Ws[k][tx * 4];
                #pragma unroll
                for (int i = 0; i < 4; i++) {
                    float a = Hs[ty * 4 + i][k];
                    acc[i][0] += a * wv.x; acc[i][1] += a * wv.y;
                    acc[i][2] += a * wv.z; acc[i][3] += a * wv.w;
                }
            }
        }
        __syncthreads();
    }
    if (ty < 24) {
        #pragma unroll
        for (int i = 0; i < 4; i++) {
            int r = row0 + ty * 4 + i;
            if (r < NN) {
                #pragma unroll
                for (int j = 0; j < 4; j++) {
                    int c = tx * 4 + j;
                    g_gv[(size_t)r * COUT + c] = acc[i][j] + __ldg(&b2[c]);
                }
            }
        }
    }
}

// ---------------- final smooth on [N,40], deg parallelized over 6 lanes ----------------
__global__ void k_passCe() {
    __shared__ float red[6][40];
    int e = blockIdx.x, t = threadIdx.x;
    int beg = g_off_e[e], deg = g_cnt_e[e];
    if (t < 240) {
        int r = t / 40, j = t - r * 40;
        float acc = 0.f;
        for (int i = r; i < deg; i += 6) {
            int vv = g_elist[beg + i];
            acc += __ldg(&g_dvis[vv]) * __ldg(&g_gv[(size_t)vv * COUT + j]);
        }
        red[r][j] = acc;
    }
    __syncthreads();
    if (t < 40) {
        float s = red[0][t] + red[1][t] + red[2][t] + red[3][t] + red[4][t] + red[5][t];
        g_ef2[(size_t)e * COUT + t] = g_deinv[e] * s;
    }
}
__global__ void k_passCn(float* __restrict__ out) {
    __shared__ float red[6][40];
    int v = blockIdx.x, t = threadIdx.x;
    int beg = g_off_n[v], deg = g_cnt_v[v];
    if (t < 240) {
        int r = t / 40, j = t - r * 40;
        float acc = 0.f;
        for (int i = r; i < deg; i += 6) {
            int e = g_nlist[beg + i];
            acc += __ldg(&g_ef2[(size_t)e * COUT + j]);
        }
        red[r][j] = acc;
    }
    __syncthreads();
    if (t < 40) {
        float s = red[0][t] + red[1][t] + red[2][t] + red[3][t] + red[4][t] + red[5][t];
        out[(size_t)v * COUT + t] = g_dvis[v] * s;
    }
}

// ---------------- launch ----------------
extern "C" void kernel_launch(void* const* d_in, const int* in_sizes, int n_in,
                              void* d_out, int out_size) {
    const float* x  = (const float*)d_in[0];   // [4, NN, 256]
    const float* W1 = (const float*)d_in[1];   // [4, 256, 256]
    const float* b1 = (const float*)d_in[2];   // [4, 256] -> flat [1024]
    const float* W2 = (const float*)d_in[3];   // [1024, 40]
    const float* b2 = (const float*)d_in[4];   // [40]
    const int*   ni = (const int*)d_in[5];     // node_idx [NNZ]
    const int*   ei = (const int*)d_in[6];     // edge_idx [NNZ]
    int nnz = in_sizes[5];
    float* out = (float*)d_out;

    k_zero  <<<(NN + 255) / 256, 256>>>();
    k_degree<<<(nnz + 255) / 256, 256>>>(ni, ei, nnz);
    k_dvde  <<<(NN + 255) / 256, 256>>>();
    k_scan_e<<<1, 1024>>>();
    k_scan_n<<<1, 1024>>>();
    k_fill  <<<(nnz + 255) / 256, 256>>>(ni, ei, nnz);
    k_t1    <<<NE, 32>>>();
    k_s     <<<NN, 32>>>();
    k_passA <<<NE, 256>>>(x);
    {
        dim3 grid((NE + 127) / 128, 4, 4);
        k_egemm<<<grid, 256>>>(W1);
    }
    k_passB <<<NN, 256>>>(b1);
    k_gemm2 <<<(NN + GM - 1) / GM, 256>>>(W2, b2);
    k_passCe<<<NE, 256>>>();
    k_passCn<<<NN, 256>>>(out);
}

// round 4
// speedup vs baseline: 2.2158x; 1.4205x over previous
#include <cuda_runtime.h>
#include <cuda_fp16.h>
#include <cstdint>

#define NN   50000
#define NE   20000
#define NNZV 1600000
#define CH   1024   // concat(4) * hid(256)
#define CIN  256
#define COUT 40

// ---------------- device scratch (static; no allocations) ----------------
__device__ int   g_cnt_v[NN];
__device__ int   g_cnt_e[NE];
__device__ int   g_cur_v[NN];
__device__ int   g_cur_e[NE];
__device__ int   g_off_e[NE];
__device__ int   g_off_n[NN];
__device__ int   g_elist[NNZV];   // nodes grouped by edge
__device__ int   g_nlist[NNZV];   // edges grouped by node
__device__ float g_dvis[NN];
__device__ float g_deinv[NE];
__device__ float g_t1[NE];
__device__ float g_s[NN];
__device__ __half g_xh[51200000]; // [4][NN][256] fp16, prescaled by dv_is
__device__ float g_z [20480000];  // [NE][CH] fp32
__device__ __half g_z2h[20480000];// [NE][CH] fp16
__device__ float g_hidden[51200000]; // [NN][CH]
__device__ float g_gv[2000000];   // [NN][COUT] (prescaled by dv_is)
__device__ float g_ef2[800000];   // [NE][COUT]

// ---------------- f32x2 packed math helpers ----------------
__device__ __forceinline__ void ffma2(unsigned long long &d, unsigned long long a, unsigned long long b) {
    asm("fma.rn.f32x2 %0, %1, %2, %0;" : "+l"(d) : "l"(a), "l"(b));
}
__device__ __forceinline__ unsigned long long bcast2(float x) {
    unsigned long long r;
    asm("mov.b64 %0, {%1, %1};" : "=l"(r) : "f"(x));
    return r;
}
__device__ __forceinline__ float lo32(unsigned long long v) { return __uint_as_float((unsigned)v); }
__device__ __forceinline__ float hi32(unsigned long long v) { return __uint_as_float((unsigned)(v >> 32)); }

// ---------------- CSR construction ----------------
__global__ void k_zero() {
    int i = blockIdx.x * blockDim.x + threadIdx.x;
    if (i < NN) { g_cnt_v[i] = 0; g_cur_v[i] = 0; }
    if (i < NE) { g_cnt_e[i] = 0; g_cur_e[i] = 0; }
}

__global__ void k_degree(const int* __restrict__ ni, const int* __restrict__ ei, int nnz) {
    int i = blockIdx.x * blockDim.x + threadIdx.x;
    if (i < nnz) {
        atomicAdd(&g_cnt_v[ni[i]], 1);
        atomicAdd(&g_cnt_e[ei[i]], 1);
    }
}

__global__ void k_dvde() {
    int i = blockIdx.x * blockDim.x + threadIdx.x;
    if (i < NN) {
        int c = g_cnt_v[i];
        g_dvis[i] = (c > 0) ? rsqrtf((float)c) : 0.f;
    }
    if (i < NE) {
        int c = g_cnt_e[i];
        g_deinv[i] = (c > 0) ? 1.f / (float)c : 0.f;
    }
}

__device__ void scan_body(const int* __restrict__ cnt, int* __restrict__ off, int n) {
    __shared__ int warpsum[32];
    int t = threadIdx.x;
    int lane = t & 31, wid = t >> 5;
    int chunk = (n + 1023) >> 10;
    int s0 = t * chunk;
    int sum = 0;
    for (int i = 0; i < chunk; i++) { int idx = s0 + i; if (idx < n) sum += cnt[idx]; }
    int v = sum;
    #pragma unroll
    for (int o = 1; o < 32; o <<= 1) {
        int u = __shfl_up_sync(0xFFFFFFFFu, v, o);
        if (lane >= o) v += u;
    }
    if (lane == 31) warpsum[wid] = v;
    __syncthreads();
    if (wid == 0) {
        int w = warpsum[lane];
        #pragma unroll
        for (int o = 1; o < 32; o <<= 1) {
            int u = __shfl_up_sync(0xFFFFFFFFu, w, o);
            if (lane >= o) w += u;
        }
        warpsum[lane] = w;
    }
    __syncthreads();
    int excl = v - sum + ((wid > 0) ? warpsum[wid - 1] : 0);
    int run = excl;
    for (int i = 0; i < chunk; i++) { int idx = s0 + i; if (idx < n) { off[idx] = run; run += cnt[idx]; } }
}
__global__ void k_scan_e() { scan_body(g_cnt_e, g_off_e, NE); }
__global__ void k_scan_n() { scan_body(g_cnt_v, g_off_n, NN); }

__global__ void k_fill(const int* __restrict__ ni, const int* __restrict__ ei, int nnz) {
    int i = blockIdx.x * blockDim.x + threadIdx.x;
    if (i < nnz) {
        int v = ni[i], e = ei[i];
        int p = atomicAdd(&g_cur_e[e], 1);
        g_elist[g_off_e[e] + p] = v;
        int q = atomicAdd(&g_cur_v[v], 1);
        g_nlist[g_off_n[v] + q] = e;
    }
}

// ---------------- x -> fp16 table, prescaled by dv_is ----------------
__global__ void k_cvt(const float* __restrict__ x) {
    int tid = blockIdx.x * blockDim.x + threadIdx.x;
    const int quarters = (4 * NN * CIN) / 4;   // 12.8M
    if (tid < quarters) {
        int lin = tid * 4;
        int row = lin >> 8;          // index in [0, 4*NN)
        int node = row % NN;
        float w = g_dvis[node];
        float4 xv = *(const float4*)(x + lin);
        __half2 h0 = __floats2half2_rn(w * xv.x, w * xv.y);
        __half2 h1 = __floats2half2_rn(w * xv.z, w * xv.w);
        uint2 o;
        o.x = *(unsigned*)&h0;
        o.y = *(unsigned*)&h1;
        *(uint2*)&g_xh[lin] = o;
    }
}

// ---------------- s = S * 1  (for bias term) ----------------
__global__ void k_t1() {
    int e = blockIdx.x, lane = threadIdx.x;
    int beg = g_off_e[e], deg = g_cnt_e[e];
    float acc = 0.f;
    for (int i = lane; i < deg; i += 32) acc += g_dvis[g_elist[beg + i]];
    #pragma unroll
    for (int o = 16; o; o >>= 1) acc += __shfl_down_sync(0xFFFFFFFFu, acc, o);
    if (lane == 0) g_t1[e] = g_deinv[e] * acc;
}
__global__ void k_s() {
    int v = blockIdx.x, lane = threadIdx.x;
    int beg = g_off_n[v], deg = g_cnt_v[v];
    float acc = 0.f;
    for (int i = lane; i < deg; i += 32) acc += g_t1[g_nlist[beg + i]];
    #pragma unroll
    for (int o = 16; o; o >>= 1) acc += __shfl_down_sync(0xFFFFFFFFu, acc, o);
    if (lane == 0) g_s[v] = g_dvis[v] * acc;
}

// ---------------- pass A: z[e][:] = de_inv[e] * sum_{v in e} xh[v][:] (xh prescaled) ----------------
// 128 threads: thread t owns 8 channels. branch b = t>>5, in-branch col = (t&31)*8.
__global__ void k_passA() {
    __shared__ int svv[128];
    int e = blockIdx.x, t = threadIdx.x;
    int beg = g_off_e[e], deg = g_cnt_e[e];
    int b = t >> 5, c = (t & 31) * 8;
    const __half* xb = g_xh + (size_t)b * NN * CIN + c;
    float a0 = 0.f, a1 = 0.f, a2 = 0.f, a3 = 0.f, a4 = 0.f, a5 = 0.f, a6 = 0.f, a7 = 0.f;
    for (int base = 0; base < deg; base += 128) {
        int m = min(128, deg - base);
        __syncthreads();
        if (t < m) svv[t] = g_elist[beg + base + t];
        __syncthreads();
        #pragma unroll 4
        for (int i = 0; i < m; i++) {
            uint4 rv = *(const uint4*)(xb + (size_t)svv[i] * CIN);
            float2 f0 = __half22float2(*(__half2*)&rv.x);
            float2 f1 = __half22float2(*(__half2*)&rv.y);
            float2 f2 = __half22float2(*(__half2*)&rv.z);
            float2 f3 = __half22float2(*(__half2*)&rv.w);
            a0 += f0.x; a1 += f0.y; a2 += f1.x; a3 += f1.y;
            a4 += f2.x; a5 += f2.y; a6 += f3.x; a7 += f3.y;
        }
    }
    float sc = g_deinv[e];
    size_t o = (size_t)e * CH + t * 8;
    float4 o0 = make_float4(sc * a0, sc * a1, sc * a2, sc * a3);
    float4 o1 = make_float4(sc * a4, sc * a5, sc * a6, sc * a7);
    *(float4*)&g_z[o]     = o0;
    *(float4*)&g_z[o + 4] = o1;
}

// ---------------- edge GEMM: z2h = z @ blockdiag(W1[b]), packed f32x2, fp16 output ----------------
__global__ void k_egemm(const float* __restrict__ W1) {
    __shared__ __align__(16) float As[16][130];
    __shared__ float Bs[16][64];
    int b = blockIdx.z;
    int row0 = blockIdx.x * 128;
    int col0 = blockIdx.y * 64;
    int t = threadIdx.x;
    int tx = t & 15, ty = t >> 4;
    unsigned long long acc[4][4];
    #pragma unroll
    for (int p = 0; p < 4; p++)
        #pragma unroll
        for (int j = 0; j < 4; j++) acc[p][j] = 0ull;
    const float* Wb = W1 + b * 65536;
    for (int k0 = 0; k0 < 256; k0 += 16) {
        #pragma unroll
        for (int i = 0; i < 8; i++) {
            int lin = t + 256 * i;
            int m = lin >> 4, k = lin & 15;
            int r = row0 + m;
            As[k][m] = (r < NE) ? g_z[(size_t)r * CH + b * 256 + k0 + k] : 0.f;
        }
        #pragma unroll
        for (int i = 0; i < 4; i++) {
            int lin = t + 256 * i;
            int k2 = lin >> 6, n2 = lin & 63;
            Bs[k2][n2] = Wb[(k0 + k2) * 256 + col0 + n2];
        }
        __syncthreads();
        #pragma unroll
        for (int k = 0; k < 16; k++) {
            unsigned long long a0 = *(const unsigned long long*)&As[k][ty * 8 + 0];
            unsigned long long a1 = *(const unsigned long long*)&As[k][ty * 8 + 2];
            unsigned long long a2 = *(const unsigned long long*)&As[k][ty * 8 + 4];
            unsigned long long a3 = *(const unsigned long long*)&As[k][ty * 8 + 6];
            float4 bv = *(const float4*)&Bs[k][tx * 4];
            unsigned long long b0 = bcast2(bv.x), b1 = bcast2(bv.y);
            unsigned long long b2 = bcast2(bv.z), b3 = bcast2(bv.w);
            ffma2(acc[0][0], a0, b0); ffma2(acc[0][1], a0, b1); ffma2(acc[0][2], a0, b2); ffma2(acc[0][3], a0, b3);
            ffma2(acc[1][0], a1, b0); ffma2(acc[1][1], a1, b1); ffma2(acc[1][2], a1, b2); ffma2(acc[1][3], a1, b3);
            ffma2(acc[2][0], a2, b0); ffma2(acc[2][1], a2, b1); ffma2(acc[2][2], a2, b2); ffma2(acc[2][3], a2, b3);
            ffma2(acc[3][0], a3, b0); ffma2(acc[3][1], a3, b1); ffma2(acc[3][2], a3, b2); ffma2(acc[3][3], a3, b3);
        }
        __syncthreads();
    }
    #pragma unroll
    for (int p = 0; p < 4; p++) {
        int r0 = row0 + ty * 8 + 2 * p;
        size_t cb = (size_t)b * 256 + col0 + tx * 4;
        if (r0 < NE) {
            __half2 h0 = __floats2half2_rn(lo32(acc[p][0]), lo32(acc[p][1]));
            __half2 h1 = __floats2half2_rn(lo32(acc[p][2]), lo32(acc[p][3]));
            uint2 o; o.x = *(unsigned*)&h0; o.y = *(unsigned*)&h1;
            *(uint2*)&g_z2h[(size_t)r0 * CH + cb] = o;
        }
        if (r0 + 1 < NE) {
            __half2 h0 = __floats2half2_rn(hi32(acc[p][0]), hi32(acc[p][1]));
            __half2 h1 = __floats2half2_rn(hi32(acc[p][2]), hi32(acc[p][3]));
            uint2 o; o.x = *(unsigned*)&h0; o.y = *(unsigned*)&h1;
            *(uint2*)&g_z2h[(size_t)(r0 + 1) * CH + cb] = o;
        }
    }
}

// ---------------- pass B: hidden[v][:] = relu(dv_is[v]*sum z2h + s[v]*b1[:]) ----------------
__global__ void k_passB(const float* __restrict__ b1) {
    __shared__ int see[128];
    int v = blockIdx.x, t = threadIdx.x;
    int beg = g_off_n[v], deg = g_cnt_v[v];
    const __half* zb = g_z2h + t * 8;
    float a0 = 0.f, a1 = 0.f, a2 = 0.f, a3 = 0.f, a4 = 0.f, a5 = 0.f, a6 = 0.f, a7 = 0.f;
    for (int base = 0; base < deg; base += 128) {
        int m = min(128, deg - base);
        __syncthreads();
        if (t < m) see[t] = g_nlist[beg + base + t];
        __syncthreads();
        #pragma unroll 4
        for (int i = 0; i < m; i++) {
            uint4 rv = *(const uint4*)(zb + (size_t)see[i] * CH);
            float2 f0 = __half22float2(*(__half2*)&rv.x);
            float2 f1 = __half22float2(*(__half2*)&rv.y);
            float2 f2 = __half22float2(*(__half2*)&rv.z);
            float2 f3 = __half22float2(*(__half2*)&rv.w);
            a0 += f0.x; a1 += f0.y; a2 += f1.x; a3 += f1.y;
            a4 += f2.x; a5 += f2.y; a6 += f3.x; a7 += f3.y;
        }
    }
    float w = g_dvis[v], sv = g_s[v];
    int c = t * 8;
    float4 bb0 = *(const float4*)&b1[c];
    float4 bb1 = *(const float4*)&b1[c + 4];
    float4 o0, o1;
    o0.x = fmaxf(w * a0 + sv * bb0.x, 0.f);
    o0.y = fmaxf(w * a1 + sv * bb0.y, 0.f);
    o0.z = fmaxf(w * a2 + sv * bb0.z, 0.f);
    o0.w = fmaxf(w * a3 + sv * bb0.w, 0.f);
    o1.x = fmaxf(w * a4 + sv * bb1.x, 0.f);
    o1.y = fmaxf(w * a5 + sv * bb1.y, 0.f);
    o1.z = fmaxf(w * a6 + sv * bb1.z, 0.f);
    o1.w = fmaxf(w * a7 + sv * bb1.w, 0.f);
    size_t o = (size_t)v * CH + c;
    *(float4*)&g_hidden[o]     = o0;
    *(float4*)&g_hidden[o + 4] = o1;
}

// ---------------- GEMM2: gv = dv_is * (hidden @ W2 + b2), f32x2 ----------------
#define GM 96
#define GK 32
__global__ void k_gemm2(const float* __restrict__ W2, const float* __restrict__ b2) {
    __shared__ float Hs[GM][GK + 1];
    __shared__ __align__(16) float Ws[GK][40];
    int row0 = blockIdx.x * GM;
    int t = threadIdx.x;
    int tx = t % 10, ty = t / 10;
    unsigned long long acc[4][2];
    #pragma unroll
    for (int i = 0; i < 4; i++) { acc[i][0] = 0ull; acc[i][1] = 0ull; }
    for (int k0 = 0; k0 < CH; k0 += GK) {
        #pragma unroll
        for (int i = 0; i < 12; i++) {
            int lin = t + 256 * i;
            int m = lin >> 5, k = lin & 31;
            int r = row0 + m;
            Hs[m][k] = (r < NN) ? g_hidden[(size_t)r * CH + k0 + k] : 0.f;
        }
        #pragma unroll
        for (int i = 0; i < 5; i++) {
            int lin = t + 256 * i;
            int k = lin / 40, j = lin % 40;
            Ws[k][j] = W2[(k0 + k) * 40 + j];
        }
        __syncthreads();
        if (ty < 24) {
            #pragma unroll
            for (int k = 0; k < GK; k++) {
                unsigned long long w0 = *(const unsigned long long*)&Ws[k][tx * 4];
                unsigned long long w1 = *(const unsigned long long*)&Ws[k][tx * 4 + 2];
                #pragma unroll
                for (int i = 0; i < 4; i++) {
                    unsigned long long au = bcast2(Hs[ty * 4 + i][k]);
                    ffma2(acc[i][0], au, w0);
                    ffma2(acc[i][1], au, w1);
                }
            }
        }
        __syncthreads();
    }
    if (ty < 24) {
        #pragma unroll
        for (int i = 0; i < 4; i++) {
            int r = row0 + ty * 4 + i;
            if (r < NN) {
                float w = g_dvis[r];
                int c = tx * 4;
                float4 o;
                o.x = w * (lo32(acc[i][0]) + __ldg(&b2[c + 0]));
                o.y = w * (hi32(acc[i][0]) + __ldg(&b2[c + 1]));
                o.z = w * (lo32(acc[i][1]) + __ldg(&b2[c + 2]));
                o.w = w * (hi32(acc[i][1]) + __ldg(&b2[c + 3]));
                *(float4*)&g_gv[(size_t)r * COUT + c] = o;
            }
        }
    }
}

// ---------------- final smooth on [N,40] ----------------
__global__ void k_passCe() {
    __shared__ float red[6][40];
    int e = blockIdx.x, t = threadIdx.x;
    int beg = g_off_e[e], deg = g_cnt_e[e];
    if (t < 240) {
        int r = t / 40, j = t - r * 40;
        float acc = 0.f;
        for (int i = r; i < deg; i += 6) {
            int vv = g_elist[beg + i];
            acc += __ldg(&g_gv[(size_t)vv * COUT + j]);
        }
        red[r][j] = acc;
    }
    __syncthreads();
    if (t < 40) {
        float s = red[0][t] + red[1][t] + red[2][t] + red[3][t] + red[4][t] + red[5][t];
        g_ef2[(size_t)e * COUT + t] = g_deinv[e] * s;
    }
}
__global__ void k_passCn(float* __restrict__ out) {
    __shared__ float red[6][40];
    int v = blockIdx.x, t = threadIdx.x;
    int beg = g_off_n[v], deg = g_cnt_v[v];
    if (t < 240) {
        int r = t / 40, j = t - r * 40;
        float acc = 0.f;
        for (int i = r; i < deg; i += 6) {
            int e = g_nlist[beg + i];
            acc += __ldg(&g_ef2[(size_t)e * COUT + j]);
        }
        red[r][j] = acc;
    }
    __syncthreads();
    if (t < 40) {
        float s = red[0][t] + red[1][t] + red[2][t] + red[3][t] + red[4][t] + red[5][t];
        out[(size_t)v * COUT + t] = g_dvis[v] * s;
    }
}

// ---------------- launch ----------------
extern "C" void kernel_launch(void* const* d_in, const int* in_sizes, int n_in,
                              void* d_out, int out_size) {
    const float* x  = (const float*)d_in[0];   // [4, NN, 256]
    const float* W1 = (const float*)d_in[1];   // [4, 256, 256]
    const float* b1 = (const float*)d_in[2];   // [4, 256] -> flat [1024]
    const float* W2 = (const float*)d_in[3];   // [1024, 40]
    const float* b2 = (const float*)d_in[4];   // [40]
    const int*   ni = (const int*)d_in[5];     // node_idx [NNZ]
    const int*   ei = (const int*)d_in[6];     // edge_idx [NNZ]
    int nnz = in_sizes[5];
    float* out = (float*)d_out;

    k_zero  <<<(NN + 255) / 256, 256>>>();
    k_degree<<<(nnz + 255) / 256, 256>>>(ni, ei, nnz);
    k_dvde  <<<(NN + 255) / 256, 256>>>();
    k_scan_e<<<1, 1024>>>();
    k_scan_n<<<1, 1024>>>();
    k_fill  <<<(nnz + 255) / 256, 256>>>(ni, ei, nnz);
    k_cvt   <<<(4 * NN * CIN / 4 + 255) / 256, 256>>>(x);
    k_t1    <<<NE, 32>>>();
    k_s     <<<NN, 32>>>();
    k_passA <<<NE, 128>>>();
    {
        dim3 grid((NE + 127) / 128, 4, 4);
        k_egemm<<<grid, 256>>>(W1);
    }
    k_passB <<<NN, 128>>>(b1);
    k_gemm2 <<<(NN + GM - 1) / GM, 256>>>(W2, b2);
    k_passCe<<<NE, 256>>>();
    k_passCn<<<NN, 256>>>(out);
}